// round 4
// baseline (speedup 1.0000x reference)
#include <cuda_runtime.h>
#include <cstdint>

// PointPillars scatter, inverted as index-map + gather.
// B=4, C=64, H=512, W=512, P=409600 (P read from in_sizes for safety).
#define B_ 4
#define C_ 64
#define H_ 512
#define W_ 512
#define HW_ (H_ * W_)        // 262144 = 2^18
#define BHW_ (B_ * HW_)      // 1048576

// 4 MB scratch: last-writer pillar index per BEV cell (-1 = empty).
__device__ int g_map[BHW_];

// ---------------------------------------------------------------------------
// Kernel 1: init map to -1 (vectorized int4).
__global__ void k_init_map() {
    int i = blockIdx.x * blockDim.x + threadIdx.x;
    if (i < BHW_ / 4) {
        reinterpret_cast<int4*>(g_map)[i] = make_int4(-1, -1, -1, -1);
    }
}

// ---------------------------------------------------------------------------
// Kernel 2: scatter pillar indices. atomicMax => highest pillar index wins,
// which equals sequential last-write-wins of the reference.
__global__ void k_scatter_idx(const int* __restrict__ coords, int P) {
    int p = blockIdx.x * blockDim.x + threadIdx.x;
    if (p >= P) return;
    int4 c = reinterpret_cast<const int4*>(coords)[p];  // [b, z, y, x]
    int b = c.x, y = c.z, x = c.w;
    if ((unsigned)y < H_ && (unsigned)x < W_) {
        atomicMax(&g_map[(b * H_ + y) * W_ + x], p);
    }
}

// ---------------------------------------------------------------------------
// Kernel 3: gather. One thread per BEV cell owns all 64 channels.
// Feature row read: 16x float4 = 256B contiguous per occupied cell.
// Output writes: stride HW_ across channels, coalesced across the warp in w.
__global__ void __launch_bounds__(256) k_gather(const float* __restrict__ feat,
                                                float* __restrict__ out) {
    int s = blockIdx.x * blockDim.x + threadIdx.x;   // 0 .. BHW_-1
    int b  = s >> 18;            // / HW_
    int sp = s & (HW_ - 1);      // within-batch spatial index

    int pid = g_map[s];

    float4 v[16];
    if (pid >= 0) {
        const float4* fp = reinterpret_cast<const float4*>(feat + (size_t)pid * C_);
#pragma unroll
        for (int i = 0; i < 16; i++) v[i] = fp[i];
    } else {
#pragma unroll
        for (int i = 0; i < 16; i++) v[i] = make_float4(0.f, 0.f, 0.f, 0.f);
    }

    float* op = out + (size_t)b * (C_ * HW_) + sp;
#pragma unroll
    for (int i = 0; i < 16; i++) {
        op[(size_t)(4 * i + 0) * HW_] = v[i].x;
        op[(size_t)(4 * i + 1) * HW_] = v[i].y;
        op[(size_t)(4 * i + 2) * HW_] = v[i].z;
        op[(size_t)(4 * i + 3) * HW_] = v[i].w;
    }
}

// ---------------------------------------------------------------------------
extern "C" void kernel_launch(void* const* d_in, const int* in_sizes, int n_in,
                              void* d_out, int out_size) {
    const float* feat   = (const float*)d_in[0];   // [P, C] float32
    const int*   coords = (const int*)d_in[1];     // [P, 4] int32
    int P = in_sizes[1] / 4;

    k_init_map<<<(BHW_ / 4 + 255) / 256, 256>>>();
    k_scatter_idx<<<(P + 255) / 256, 256>>>(coords, P);
    k_gather<<<BHW_ / 256, 256>>>(feat, (float*)d_out);
}

// round 5
// speedup vs baseline: 1.0393x; 1.0393x over previous
#include <cuda_runtime.h>
#include <cstdint>

// PointPillars scatter, inverted as index-map + gather.
// B=4, C=64, H=512, W=512, P=409600 (P read from in_sizes for safety).
//
// Init-free map: g_map holds (pid+1), 0 = empty. __device__ globals are
// zero-initialized at module load, and the gather kernel resets every
// nonzero cell back to 0 after consuming it, so each graph replay sees a
// clean map without a dedicated init kernel. scatter -> gather ordering on
// the capture stream guarantees the reset lands before the next replay's
// atomics.
#define B_ 4
#define C_ 64
#define H_ 512
#define W_ 512
#define HW_ (H_ * W_)        // 262144 = 2^18
#define BHW_ (B_ * HW_)      // 1048576

__device__ int g_map[BHW_];  // zero-initialized at load; 0 = empty

// ---------------------------------------------------------------------------
// Kernel 1: scatter (pid+1) per pillar. atomicMax => highest pillar index
// wins, which equals the reference's sequential last-write-wins.
__global__ void __launch_bounds__(256) k_scatter_idx(const int* __restrict__ coords, int P) {
    int p = blockIdx.x * blockDim.x + threadIdx.x;
    if (p >= P) return;
    int4 c = reinterpret_cast<const int4*>(coords)[p];  // [b, z, y, x]
    int b = c.x, y = c.z, x = c.w;
    if ((unsigned)y < H_ && (unsigned)x < W_) {
        atomicMax(&g_map[(b * H_ + y) * W_ + x], p + 1);
    }
}

// ---------------------------------------------------------------------------
// Kernel 2: gather + self-clean. One thread per BEV cell owns all 64
// channels. Feature row read: 16x float4 = 256B contiguous per occupied
// cell (streaming). Output writes: stride HW_ across channels, coalesced
// across the warp in w (streaming stores — don't thrash L2). Nonzero map
// entries are reset to 0 for the next replay.
__global__ void __launch_bounds__(256) k_gather(const float* __restrict__ feat,
                                                float* __restrict__ out) {
    int s = blockIdx.x * blockDim.x + threadIdx.x;   // 0 .. BHW_-1
    int b  = s >> 18;            // / HW_
    int sp = s & (HW_ - 1);      // within-batch spatial index

    int v = g_map[s];

    float4 r[16];
    if (v > 0) {
        g_map[s] = 0;            // self-clean for next graph replay
        const float4* fp = reinterpret_cast<const float4*>(feat + (size_t)(v - 1) * C_);
#pragma unroll
        for (int i = 0; i < 16; i++) r[i] = __ldcs(fp + i);
    } else {
#pragma unroll
        for (int i = 0; i < 16; i++) r[i] = make_float4(0.f, 0.f, 0.f, 0.f);
    }

    float* op = out + (size_t)b * (C_ * HW_) + sp;
#pragma unroll
    for (int i = 0; i < 16; i++) {
        __stcs(op + (size_t)(4 * i + 0) * HW_, r[i].x);
        __stcs(op + (size_t)(4 * i + 1) * HW_, r[i].y);
        __stcs(op + (size_t)(4 * i + 2) * HW_, r[i].z);
        __stcs(op + (size_t)(4 * i + 3) * HW_, r[i].w);
    }
}

// ---------------------------------------------------------------------------
extern "C" void kernel_launch(void* const* d_in, const int* in_sizes, int n_in,
                              void* d_out, int out_size) {
    const float* feat   = (const float*)d_in[0];   // [P, C] float32
    const int*   coords = (const int*)d_in[1];     // [P, 4] int32
    int P = in_sizes[1] / 4;

    k_scatter_idx<<<(P + 255) / 256, 256>>>(coords, P);
    k_gather<<<BHW_ / 256, 256>>>(feat, (float*)d_out);
}